// round 1
// baseline (speedup 1.0000x reference)
#include <cuda_runtime.h>
#include <cuda_bf16.h>
#include <math.h>

// Problem constants
#define BT   32768   // tokens
#define DIN  768
#define DH   384
#define DH2  192
#define DOUT 256
#define NE   5

// ---------------- scratch (device globals; no allocation allowed) ----------------
__device__ float g_bufA[(size_t)BT * DH];   // 50 MB
__device__ float g_bufB[(size_t)BT * DH];   // 50 MB
__device__ float g_Y[(size_t)BT * DOUT];    // 33 MB
__device__ float g_V[(size_t)BT * DOUT];    // 33 MB
__device__ int   g_eidx[BT];
__device__ int   g_perm[BT];
__device__ int   g_rowexp[BT];
__device__ int   g_cnt[NE];
__device__ int   g_off[NE + 1];
__device__ int   g_cur[NE];

// ---------------- generic tiled SGEMM: C[m,n] = sum_k A[m,k]*W[n,k] + bias[n] ------
// 64x64 tile, BK=16, 256 threads, 4x4 microtile per thread.
// seg != nullptr => expert-segmented mode: blockIdx.z = expert, rows are the
// compacted range [seg[e], seg[e+1]). gather (optional) maps compacted row -> A row.
__global__ __launch_bounds__(256)
void gemm64(const float* __restrict__ A, const int* __restrict__ gather,
            const float* __restrict__ W, const float* __restrict__ bias,
            float* __restrict__ C, int N, int K,
            const int* __restrict__ seg, long wstride, int bstride, int Mtot)
{
    __shared__ float As[16][68];
    __shared__ float Ws[16][68];

    int e = 0, rowbase = 0, segM = Mtot;
    if (seg) { e = blockIdx.z; rowbase = seg[e]; segM = seg[e + 1] - rowbase; }
    int mt = blockIdx.x * 64;
    if (mt >= segM) return;

    const float* Wp = W + (long)e * wstride;
    const float* bp = bias + (long)e * bstride;
    int n0 = blockIdx.y * 64;

    int t   = threadIdx.x;
    int lr  = t >> 2;            // 0..63 : row within tile for loading
    int kq  = (t & 3) * 4;       // 0,4,8,12 : k quad within BK
    int tx  = t & 15;            // 0..15 : N microtile
    int ty  = t >> 4;            // 0..15 : M microtile

    int mload = mt + lr; if (mload > segM - 1) mload = segM - 1;
    int arow_c = rowbase + mload;
    int arow = gather ? gather[arow_c] : arow_c;
    const float* Arow = A  + (size_t)arow * K;
    const float* Wrow = Wp + (size_t)(n0 + lr) * K;

    float acc[4][4];
    #pragma unroll
    for (int i = 0; i < 4; i++)
        #pragma unroll
        for (int j = 0; j < 4; j++) acc[i][j] = 0.f;

    for (int k0 = 0; k0 < K; k0 += 16) {
        float4 av = *(const float4*)(Arow + k0 + kq);
        float4 wv = *(const float4*)(Wrow + k0 + kq);
        __syncthreads();
        As[kq + 0][lr] = av.x; As[kq + 1][lr] = av.y;
        As[kq + 2][lr] = av.z; As[kq + 3][lr] = av.w;
        Ws[kq + 0][lr] = wv.x; Ws[kq + 1][lr] = wv.y;
        Ws[kq + 2][lr] = wv.z; Ws[kq + 3][lr] = wv.w;
        __syncthreads();
        #pragma unroll
        for (int kk = 0; kk < 16; kk++) {
            float a[4], b[4];
            #pragma unroll
            for (int i = 0; i < 4; i++) a[i] = As[kk][ty * 4 + i];
            #pragma unroll
            for (int j = 0; j < 4; j++) b[j] = Ws[kk][tx * 4 + j];
            #pragma unroll
            for (int i = 0; i < 4; i++)
                #pragma unroll
                for (int j = 0; j < 4; j++) acc[i][j] = fmaf(a[i], b[j], acc[i][j]);
        }
    }

    #pragma unroll
    for (int i = 0; i < 4; i++) {
        int m = mt + ty * 4 + i;
        if (m < segM) {
            float* crow = C + (size_t)(rowbase + m) * N + n0;
            #pragma unroll
            for (int j = 0; j < 4; j++)
                crow[tx * 4 + j] = acc[i][j] + bp[n0 + tx * 4 + j];
        }
    }
}

// ---------------- row LayerNorm (+optional ReLU), warp per row -------------------
__global__ void ln_rows(const float* __restrict__ in, float* __restrict__ out, int Ncols,
                        const float* __restrict__ g, const float* __restrict__ b,
                        int gstride, int doRelu, const int* __restrict__ rowexp, int M)
{
    int row = blockIdx.x * 8 + (threadIdx.x >> 5);
    if (row >= M) return;
    int lane = threadIdx.x & 31;
    int e = rowexp ? rowexp[row] : 0;
    const float* ip = in + (size_t)row * Ncols;
    int nw = Ncols >> 5;   // <= 12

    float v[12];
    float s = 0.f;
    for (int i = 0; i < nw; i++) { v[i] = ip[lane + i * 32]; s += v[i]; }
    #pragma unroll
    for (int o = 16; o; o >>= 1) s += __shfl_xor_sync(0xffffffffu, s, o);
    float mu = s / (float)Ncols;

    float sq = 0.f;
    for (int i = 0; i < nw; i++) { float d = v[i] - mu; sq += d * d; }
    #pragma unroll
    for (int o = 16; o; o >>= 1) sq += __shfl_xor_sync(0xffffffffu, sq, o);
    float var = sq / (float)Ncols;
    float inv = 1.0f / sqrtf(var + 1e-5f);

    const float* gp = g + (long)e * gstride;
    const float* bp = b + (long)e * gstride;
    float* op = out + (size_t)row * Ncols;
    for (int i = 0; i < nw; i++) {
        int c = lane + i * 32;
        float o2 = (v[i] - mu) * inv * gp[c] + bp[c];
        if (doRelu) o2 = fmaxf(o2, 0.f);
        op[c] = o2;
    }
}

// ---------------- router head: logits(5) + gumbel + softmax + argmax + routing ----
__global__ void routing_kernel(const float* __restrict__ h2, const float* __restrict__ rw3,
                               const float* __restrict__ rb3, const float* __restrict__ gumbel,
                               float* __restrict__ outRW, float* __restrict__ outIdx)
{
    int tok = blockIdx.x * 8 + (threadIdx.x >> 5);
    if (tok >= BT) return;
    int lane = threadIdx.x & 31;
    const float* h = h2 + (size_t)tok * DH2;

    float acc[NE];
    #pragma unroll
    for (int j = 0; j < NE; j++) acc[j] = 0.f;
    #pragma unroll
    for (int i = 0; i < DH2 / 32; i++) {
        int k = lane + i * 32;
        float hv = h[k];
        #pragma unroll
        for (int j = 0; j < NE; j++)
            acc[j] = fmaf(hv, rw3[j * DH2 + k], acc[j]);
    }
    #pragma unroll
    for (int j = 0; j < NE; j++)
        #pragma unroll
        for (int o = 16; o; o >>= 1)
            acc[j] += __shfl_xor_sync(0xffffffffu, acc[j], o);

    if (lane == 0) {
        float z[NE];
        float best = -1e30f; int bi = 0;
        #pragma unroll
        for (int j = 0; j < NE; j++) {
            float lg = acc[j] + rb3[j];
            z[j] = (lg + gumbel[(size_t)tok * NE + j]) / 0.07f;
            if (z[j] > best) { best = z[j]; bi = j; }
        }
        float ex[NE], sum = 0.f;
        #pragma unroll
        for (int j = 0; j < NE; j++) { ex[j] = expf(z[j] - best); sum += ex[j]; }
        #pragma unroll
        for (int j = 0; j < NE; j++) {
            float ys = ex[j] / sum;
            float hard = (j == bi) ? 1.f : 0.f;
            outRW[(size_t)tok * NE + j] = (hard + ys) - ys;   // straight-through, literal
        }
        outIdx[tok] = (float)bi;
        g_eidx[tok] = bi;
        atomicAdd(&g_cnt[bi], 1);
    }
}

__global__ void scan_kernel()
{
    if (threadIdx.x == 0 && blockIdx.x == 0) {
        int o = 0;
        for (int e = 0; e < NE; e++) { g_off[e] = o; g_cur[e] = o; o += g_cnt[e]; }
        g_off[NE] = o;
    }
}

__global__ void fill_perm()
{
    int t = blockIdx.x * blockDim.x + threadIdx.x;
    if (t < BT) {
        int e = g_eidx[t];
        int p = atomicAdd(&g_cur[e], 1);
        g_perm[p]   = t;
        g_rowexp[p] = e;
    }
}

// ---------------- final: LN(Y + O) scattered back to token order ------------------
__global__ void final_kernel(const float* __restrict__ Y, const float* __restrict__ O,
                             const float* __restrict__ ng, const float* __restrict__ nb,
                             float* __restrict__ outMain)
{
    int r = blockIdx.x * 8 + (threadIdx.x >> 5);
    if (r >= BT) return;
    int lane = threadIdx.x & 31;
    int e = g_rowexp[r];
    int t = g_perm[r];

    float v[8];
    float s = 0.f;
    #pragma unroll
    for (int i = 0; i < 8; i++) {
        int c = lane + i * 32;
        v[i] = Y[(size_t)r * DOUT + c] + O[(size_t)r * DOUT + c];
        s += v[i];
    }
    #pragma unroll
    for (int o = 16; o; o >>= 1) s += __shfl_xor_sync(0xffffffffu, s, o);
    float mu = s / (float)DOUT;
    float sq = 0.f;
    #pragma unroll
    for (int i = 0; i < 8; i++) { float d = v[i] - mu; sq += d * d; }
    #pragma unroll
    for (int o = 16; o; o >>= 1) sq += __shfl_xor_sync(0xffffffffu, sq, o);
    float inv = 1.0f / sqrtf(sq / (float)DOUT + 1e-5f);

    const float* gp = ng + (long)e * DOUT;
    const float* bp = nb + (long)e * DOUT;
    float* op = outMain + (size_t)t * DOUT;
    #pragma unroll
    for (int i = 0; i < 8; i++) {
        int c = lane + i * 32;
        op[c] = (v[i] - mu) * inv * gp[c] + bp[c];
    }
}

// ---------------- launch ----------------------------------------------------------
extern "C" void kernel_launch(void* const* d_in, const int* in_sizes, int n_in,
                              void* d_out, int out_size)
{
    const float* x      = (const float*)d_in[0];
    const float* gumbel = (const float*)d_in[1];
    const float* rw1  = (const float*)d_in[2];
    const float* rb1  = (const float*)d_in[3];
    const float* rg1  = (const float*)d_in[4];
    const float* rbe1 = (const float*)d_in[5];
    const float* rw2  = (const float*)d_in[6];
    const float* rb2  = (const float*)d_in[7];
    const float* rg2  = (const float*)d_in[8];
    const float* rbe2 = (const float*)d_in[9];
    const float* rw3  = (const float*)d_in[10];
    const float* rb3  = (const float*)d_in[11];
    const float* ew1  = (const float*)d_in[12];
    const float* eb1  = (const float*)d_in[13];
    const float* eg1  = (const float*)d_in[14];
    const float* ebe1 = (const float*)d_in[15];
    const float* ew2  = (const float*)d_in[16];
    const float* eb2  = (const float*)d_in[17];
    const float* eg2  = (const float*)d_in[18];
    const float* ebe2 = (const float*)d_in[19];
    const float* ew3  = (const float*)d_in[20];
    const float* eb3  = (const float*)d_in[21];
    const float* eg3  = (const float*)d_in[22];
    const float* ebe3 = (const float*)d_in[23];
    const float* wqkv = (const float*)d_in[24];
    const float* bqkv = (const float*)d_in[25];
    const float* wo   = (const float*)d_in[26];
    const float* bo   = (const float*)d_in[27];
    const float* ng   = (const float*)d_in[28];
    const float* nb   = (const float*)d_in[29];

    float* outMain = (float*)d_out;
    float* outRW   = outMain + (size_t)BT * DOUT;
    float* outIdx  = outRW   + (size_t)BT * NE;

    float *bufA, *bufB, *Yb, *Vb; int *off, *perm, *rowexp; void* cntp;
    cudaGetSymbolAddress((void**)&bufA,   g_bufA);
    cudaGetSymbolAddress((void**)&bufB,   g_bufB);
    cudaGetSymbolAddress((void**)&Yb,     g_Y);
    cudaGetSymbolAddress((void**)&Vb,     g_V);
    cudaGetSymbolAddress((void**)&off,    g_off);
    cudaGetSymbolAddress((void**)&perm,   g_perm);
    cudaGetSymbolAddress((void**)&rowexp, g_rowexp);
    cudaGetSymbolAddress(&cntp,           g_cnt);

    cudaMemsetAsync(cntp, 0, NE * sizeof(int));

    // ---- router ----
    gemm64<<<dim3(BT / 64, DH / 64, 1), 256>>>(x, nullptr, rw1, rb1, bufA, DH, DIN,
                                               nullptr, 0, 0, BT);
    ln_rows<<<BT / 8, 256>>>(bufA, bufA, DH, rg1, rbe1, 0, 1, nullptr, BT);
    gemm64<<<dim3(BT / 64, DH2 / 64, 1), 256>>>(bufA, nullptr, rw2, rb2, bufB, DH2, DH,
                                                nullptr, 0, 0, BT);
    ln_rows<<<BT / 8, 256>>>(bufB, bufB, DH2, rg2, rbe2, 0, 1, nullptr, BT);
    routing_kernel<<<BT / 8, 256>>>(bufB, rw3, rb3, gumbel, outRW, outIdx);
    scan_kernel<<<1, 32>>>();
    fill_perm<<<BT / 256, 256>>>();

    // ---- experts (compacted; sum of segments == BT) ----
    gemm64<<<dim3(BT / 64, DH / 64, NE), 256>>>(x, perm, ew1, eb1, bufA, DH, DIN,
                                                off, (long)DH * DIN, DH, BT);
    ln_rows<<<BT / 8, 256>>>(bufA, bufA, DH, eg1, ebe1, DH, 1, rowexp, BT);

    gemm64<<<dim3(BT / 64, DH / 64, NE), 256>>>(bufA, nullptr, ew2, eb2, bufB, DH, DH,
                                                off, (long)DH * DH, DH, BT);
    ln_rows<<<BT / 8, 256>>>(bufB, bufB, DH, eg2, ebe2, DH, 1, rowexp, BT);

    gemm64<<<dim3(BT / 64, DOUT / 64, NE), 256>>>(bufB, nullptr, ew3, eb3, Yb, DOUT, DH,
                                                  off, (long)DOUT * DH, DOUT, BT);
    ln_rows<<<BT / 8, 256>>>(Yb, Yb, DOUT, eg3, ebe3, DOUT, 0, rowexp, BT);

    // attention over length-1 sequence collapses to attn = V  (softmax over 1 key == 1)
    gemm64<<<dim3(BT / 64, DOUT / 64, NE), 256>>>(Yb, nullptr, wqkv + 2 * DOUT * DOUT,
                                                  bqkv + 2 * DOUT, Vb, DOUT, DOUT,
                                                  off, (long)3 * DOUT * DOUT, 3 * DOUT, BT);
    gemm64<<<dim3(BT / 64, DOUT / 64, NE), 256>>>(Vb, nullptr, wo, bo, bufA, DOUT, DOUT,
                                                  off, (long)DOUT * DOUT, DOUT, BT);

    final_kernel<<<BT / 8, 256>>>(Yb, bufA, ng, nb, outMain);
}

// round 2
// speedup vs baseline: 1.1899x; 1.1899x over previous
#include <cuda_runtime.h>
#include <cuda_bf16.h>
#include <mma.h>
#include <math.h>

using namespace nvcuda;

// Problem constants
#define BT   32768
#define DIN  768
#define DH   384
#define DH2  192
#define DOUT 256
#define NE   5

// GEMM tile config
#define BM 128
#define BN 128
#define BKK 16
#define LDS_PAD 20      // smem leading dim (floats), %4==0
#define ABUF 2560       // BM*LDS_PAD
#define BBUF 2560       // BN*LDS_PAD

// ---------------- scratch (device globals) ----------------
__device__ float g_bufA[(size_t)BT * DH];
__device__ float g_bufB[(size_t)BT * DH];
__device__ float g_Y[(size_t)BT * DOUT];
__device__ float g_wc[(size_t)NE * DOUT * DOUT];
__device__ float g_bc[NE * DOUT];
__device__ int   g_eidx[BT];
__device__ int   g_perm[BT];
__device__ int   g_rowexp[BT];
__device__ int   g_cnt[NE];
__device__ int   g_off[NE + 1];
__device__ int   g_cur[NE];

__device__ __forceinline__ float tf32r(float x) { return wmma::__float_to_tf32(x); }
__device__ __forceinline__ float4 tf32r4(float4 v) {
    v.x = tf32r(v.x); v.y = tf32r(v.y); v.z = tf32r(v.z); v.w = tf32r(v.w);
    return v;
}

// ================= tensor-core GEMM: C[m,n] = A[m,:] . W[n,:] + bias[n] =========
// SPLIT=1: 3-term split-tf32 (fp32-level accuracy, for router).
// SPLIT=0: plain tf32 (expert path).
// seg != nullptr => expert-segmented: blockIdx.z = expert, rows in [seg[e],seg[e+1]).
// gather (optional) maps compacted row -> A row.
template<int SPLIT>
__global__ void __launch_bounds__(256, SPLIT ? 1 : 2)
gemm_tc(const float* __restrict__ A, const int* __restrict__ gather,
        const float* __restrict__ W, const float* __restrict__ bias,
        float* __restrict__ C, int N, int K,
        const int* __restrict__ seg, long wstride, int bstride, int Mtot)
{
    __shared__ __align__(16) float sm[ABUF * 2 + BBUF * 2];  // 40 KB; also epilogue stage
    float* SA = sm;
    float* SB = sm + ABUF * 2;

    int e = 0, rowbase = 0, segM = Mtot;
    if (seg) { e = blockIdx.z; rowbase = seg[e]; segM = seg[e + 1] - rowbase; }
    int mt = blockIdx.x * BM;
    if (mt >= segM) return;

    const float* Wp = W + (long)e * wstride;
    const float* bp = bias + (long)e * bstride;
    int n0 = blockIdx.y * BN;

    int tid = threadIdx.x;
    int wid = tid >> 5;
    int wm  = wid >> 1;        // 0..3 -> 32-row stripe
    int wn  = wid & 1;         // 0..1 -> 64-col stripe

    // ---- loader setup: 512 float4 for A (128x16), 512 for B, 2 each/thread ----
    int idx0 = tid, idx1 = tid + 256;
    int rA0 = idx0 >> 2, cA0 = (idx0 & 3) * 4;
    int rA1 = idx1 >> 2, cA1 = (idx1 & 3) * 4;
    int mr0 = mt + rA0; if (mr0 > segM - 1) mr0 = segM - 1;
    int mr1 = mt + rA1; if (mr1 > segM - 1) mr1 = segM - 1;
    int ar0 = gather ? gather[rowbase + mr0] : rowbase + mr0;
    int ar1 = gather ? gather[rowbase + mr1] : rowbase + mr1;
    const float* ap0 = A + (size_t)ar0 * K + cA0;
    const float* ap1 = A + (size_t)ar1 * K + cA1;
    int sA0 = rA0 * LDS_PAD + cA0;
    int sA1 = rA1 * LDS_PAD + cA1;

    int nr0 = n0 + rA0; if (nr0 > N - 1) nr0 = N - 1;
    int nr1 = n0 + rA1; if (nr1 > N - 1) nr1 = N - 1;
    const float* bpt0 = Wp + (size_t)nr0 * K + cA0;
    const float* bpt1 = Wp + (size_t)nr1 * K + cA1;

    wmma::fragment<wmma::accumulator, 16, 16, 8, float> acc[2][4];
    #pragma unroll
    for (int mi = 0; mi < 2; mi++)
        #pragma unroll
        for (int ni = 0; ni < 4; ni++) wmma::fill_fragment(acc[mi][ni], 0.f);

    // preload k-block 0
    float4 ra0 = *(const float4*)(ap0);
    float4 ra1 = *(const float4*)(ap1);
    float4 rb0 = *(const float4*)(bpt0);
    float4 rb1 = *(const float4*)(bpt1);

    int nk = K / BKK;
    {
        float4 a0 = SPLIT ? ra0 : tf32r4(ra0);
        float4 a1 = SPLIT ? ra1 : tf32r4(ra1);
        float4 b0 = SPLIT ? rb0 : tf32r4(rb0);
        float4 b1 = SPLIT ? rb1 : tf32r4(rb1);
        *(float4*)(SA + sA0) = a0; *(float4*)(SA + sA1) = a1;
        *(float4*)(SB + sA0) = b0; *(float4*)(SB + sA1) = b1;
    }
    __syncthreads();

    for (int kb = 0; kb < nk; kb++) {
        int buf = kb & 1;
        if (kb + 1 < nk) {
            int k = (kb + 1) * BKK;
            ra0 = *(const float4*)(ap0 + k);
            ra1 = *(const float4*)(ap1 + k);
            rb0 = *(const float4*)(bpt0 + k);
            rb1 = *(const float4*)(bpt1 + k);
        }
        const float* sa = SA + buf * ABUF;
        const float* sb = SB + buf * BBUF;
        #pragma unroll
        for (int ks = 0; ks < 2; ks++) {
            wmma::fragment<wmma::matrix_a, 16, 16, 8, wmma::precision::tf32, wmma::row_major> a[2];
            wmma::fragment<wmma::matrix_b, 16, 16, 8, wmma::precision::tf32, wmma::col_major> b[4];
            #pragma unroll
            for (int mi = 0; mi < 2; mi++)
                wmma::load_matrix_sync(a[mi], sa + (wm * 32 + mi * 16) * LDS_PAD + ks * 8, LDS_PAD);
            #pragma unroll
            for (int ni = 0; ni < 4; ni++)
                wmma::load_matrix_sync(b[ni], sb + (wn * 64 + ni * 16) * LDS_PAD + ks * 8, LDS_PAD);

            if (SPLIT) {
                wmma::fragment<wmma::matrix_a, 16, 16, 8, wmma::precision::tf32, wmma::row_major> ah[2];
                wmma::fragment<wmma::matrix_b, 16, 16, 8, wmma::precision::tf32, wmma::col_major> bh[4];
                #pragma unroll
                for (int mi = 0; mi < 2; mi++)
                    #pragma unroll
                    for (int i = 0; i < a[mi].num_elements; i++) {
                        float h = tf32r(a[mi].x[i]);
                        ah[mi].x[i] = h;
                        a[mi].x[i] = tf32r(a[mi].x[i] - h);   // now holds lo
                    }
                #pragma unroll
                for (int ni = 0; ni < 4; ni++)
                    #pragma unroll
                    for (int i = 0; i < b[ni].num_elements; i++) {
                        float h = tf32r(b[ni].x[i]);
                        bh[ni].x[i] = h;
                        b[ni].x[i] = tf32r(b[ni].x[i] - h);   // now holds lo
                    }
                #pragma unroll
                for (int mi = 0; mi < 2; mi++)
                    #pragma unroll
                    for (int ni = 0; ni < 4; ni++) {
                        wmma::mma_sync(acc[mi][ni], ah[mi], bh[ni], acc[mi][ni]);
                        wmma::mma_sync(acc[mi][ni], ah[mi], b[ni],  acc[mi][ni]);
                        wmma::mma_sync(acc[mi][ni], a[mi],  bh[ni], acc[mi][ni]);
                    }
            } else {
                #pragma unroll
                for (int mi = 0; mi < 2; mi++)
                    #pragma unroll
                    for (int ni = 0; ni < 4; ni++)
                        wmma::mma_sync(acc[mi][ni], a[mi], b[ni], acc[mi][ni]);
            }
        }
        if (kb + 1 < nk) {
            int nb = buf ^ 1;
            float4 a0 = SPLIT ? ra0 : tf32r4(ra0);
            float4 a1 = SPLIT ? ra1 : tf32r4(ra1);
            float4 b0 = SPLIT ? rb0 : tf32r4(rb0);
            float4 b1 = SPLIT ? rb1 : tf32r4(rb1);
            *(float4*)(SA + nb * ABUF + sA0) = a0;
            *(float4*)(SA + nb * ABUF + sA1) = a1;
            *(float4*)(SB + nb * BBUF + sA0) = b0;
            *(float4*)(SB + nb * BBUF + sA1) = b1;
            __syncthreads();
        }
    }

    // ---- epilogue: stage 64 rows at a time through smem, add bias, guard ----
    __syncthreads();
    float* stage = sm;                 // 64 x 132 floats = 33.8 KB <= 40 KB
    const int SLD = 132;
    #pragma unroll
    for (int r = 0; r < 2; r++) {
        if ((wm >> 1) == r) {
            #pragma unroll
            for (int mi = 0; mi < 2; mi++)
                #pragma unroll
                for (int ni = 0; ni < 4; ni++)
                    wmma::store_matrix_sync(stage + ((wm & 1) * 32 + mi * 16) * SLD + wn * 64 + ni * 16,
                                            acc[mi][ni], SLD, wmma::mem_row_major);
        }
        __syncthreads();
        #pragma unroll
        for (int it = 0; it < 8; it++) {
            int fidx = tid + it * 256;      // 2048 float4s = 64x128
            int lrow = fidx >> 5;
            int c4 = (fidx & 31) * 4;
            int m = mt + r * 64 + lrow;
            int n = n0 + c4;
            if (m < segM && n < N) {
                float4 v = *(float4*)(stage + lrow * SLD + c4);
                float4 bv = *(const float4*)(bp + n);
                v.x += bv.x; v.y += bv.y; v.z += bv.z; v.w += bv.w;
                *(float4*)(C + (size_t)(rowbase + m) * N + n) = v;
            }
        }
        __syncthreads();
    }
}

// ---------------- fuse wo @ wv (attention collapses to V passthrough) ------------
__global__ void fuse_wo_wv(const float* __restrict__ wqkv, const float* __restrict__ bqkv,
                           const float* __restrict__ wo, const float* __restrict__ bo,
                           float* __restrict__ wc, float* __restrict__ bc)
{
    int e = blockIdx.z, n = blockIdx.y, k = threadIdx.x;
    const float* woR = wo + ((size_t)e * DOUT + n) * DOUT;
    const float* wv  = wqkv + (size_t)e * 3 * DOUT * DOUT + 2 * DOUT * DOUT;
    const float* bv  = bqkv + (size_t)e * 3 * DOUT + 2 * DOUT;
    float s = 0.f;
    for (int j = 0; j < DOUT; j++) s = fmaf(woR[j], wv[(size_t)j * DOUT + k], s);
    wc[((size_t)e * DOUT + n) * DOUT + k] = s;
    if (k == 0) {
        float sb = bo[e * DOUT + n];
        for (int j = 0; j < DOUT; j++) sb = fmaf(woR[j], bv[j], sb);
        bc[e * DOUT + n] = sb;
    }
}

// ---------------- row LayerNorm (+optional ReLU), warp per row -------------------
__global__ void ln_rows(const float* __restrict__ in, float* __restrict__ out, int Ncols,
                        const float* __restrict__ g, const float* __restrict__ b,
                        int gstride, int doRelu, const int* __restrict__ rowexp, int M)
{
    int row = blockIdx.x * 8 + (threadIdx.x >> 5);
    if (row >= M) return;
    int lane = threadIdx.x & 31;
    int e = rowexp ? rowexp[row] : 0;
    const float* ip = in + (size_t)row * Ncols;
    int nw = Ncols >> 5;

    float v[12];
    float s = 0.f;
    for (int i = 0; i < nw; i++) { v[i] = ip[lane + i * 32]; s += v[i]; }
    #pragma unroll
    for (int o = 16; o; o >>= 1) s += __shfl_xor_sync(0xffffffffu, s, o);
    float mu = s / (float)Ncols;

    float sq = 0.f;
    for (int i = 0; i < nw; i++) { float d = v[i] - mu; sq += d * d; }
    #pragma unroll
    for (int o = 16; o; o >>= 1) sq += __shfl_xor_sync(0xffffffffu, sq, o);
    float inv = 1.0f / sqrtf(sq / (float)Ncols + 1e-5f);

    const float* gp = g + (long)e * gstride;
    const float* bp = b + (long)e * gstride;
    float* op = out + (size_t)row * Ncols;
    for (int i = 0; i < nw; i++) {
        int c = lane + i * 32;
        float o2 = (v[i] - mu) * inv * gp[c] + bp[c];
        if (doRelu) o2 = fmaxf(o2, 0.f);
        op[c] = o2;
    }
}

// ---------------- router head ------------------------------------------------------
__global__ void routing_kernel(const float* __restrict__ h2, const float* __restrict__ rw3,
                               const float* __restrict__ rb3, const float* __restrict__ gumbel,
                               float* __restrict__ outRW, float* __restrict__ outIdx)
{
    int tok = blockIdx.x * 8 + (threadIdx.x >> 5);
    if (tok >= BT) return;
    int lane = threadIdx.x & 31;
    const float* h = h2 + (size_t)tok * DH2;

    float acc[NE];
    #pragma unroll
    for (int j = 0; j < NE; j++) acc[j] = 0.f;
    #pragma unroll
    for (int i = 0; i < DH2 / 32; i++) {
        int k = lane + i * 32;
        float hv = h[k];
        #pragma unroll
        for (int j = 0; j < NE; j++)
            acc[j] = fmaf(hv, rw3[j * DH2 + k], acc[j]);
    }
    #pragma unroll
    for (int j = 0; j < NE; j++)
        #pragma unroll
        for (int o = 16; o; o >>= 1)
            acc[j] += __shfl_xor_sync(0xffffffffu, acc[j], o);

    if (lane == 0) {
        float z[NE];
        float best = -1e30f; int bi = 0;
        #pragma unroll
        for (int j = 0; j < NE; j++) {
            float lg = acc[j] + rb3[j];
            z[j] = (lg + gumbel[(size_t)tok * NE + j]) / 0.07f;
            if (z[j] > best) { best = z[j]; bi = j; }
        }
        float ex[NE], sum = 0.f;
        #pragma unroll
        for (int j = 0; j < NE; j++) { ex[j] = expf(z[j] - best); sum += ex[j]; }
        #pragma unroll
        for (int j = 0; j < NE; j++) {
            float ys = ex[j] / sum;
            float hard = (j == bi) ? 1.f : 0.f;
            outRW[(size_t)tok * NE + j] = (hard + ys) - ys;
        }
        outIdx[tok] = (float)bi;
        g_eidx[tok] = bi;
        atomicAdd(&g_cnt[bi], 1);
    }
}

__global__ void scan_kernel()
{
    if (threadIdx.x == 0 && blockIdx.x == 0) {
        int o = 0;
        for (int e = 0; e < NE; e++) { g_off[e] = o; g_cur[e] = o; o += g_cnt[e]; }
        g_off[NE] = o;
    }
}

__global__ void fill_perm()
{
    int t = blockIdx.x * blockDim.x + threadIdx.x;
    if (t < BT) {
        int e = g_eidx[t];
        int p = atomicAdd(&g_cur[e], 1);
        g_perm[p]   = t;
        g_rowexp[p] = e;
    }
}

// ---------------- final: LN(Y + O) scattered back to token order ------------------
__global__ void final_kernel(const float* __restrict__ Y, const float* __restrict__ O,
                             const float* __restrict__ ng, const float* __restrict__ nb,
                             float* __restrict__ outMain)
{
    int r = blockIdx.x * 8 + (threadIdx.x >> 5);
    if (r >= BT) return;
    int lane = threadIdx.x & 31;
    int e = g_rowexp[r];
    int t = g_perm[r];

    float v[8];
    float s = 0.f;
    #pragma unroll
    for (int i = 0; i < 8; i++) {
        int c = lane + i * 32;
        v[i] = Y[(size_t)r * DOUT + c] + O[(size_t)r * DOUT + c];
        s += v[i];
    }
    #pragma unroll
    for (int o = 16; o; o >>= 1) s += __shfl_xor_sync(0xffffffffu, s, o);
    float mu = s / (float)DOUT;
    float sq = 0.f;
    #pragma unroll
    for (int i = 0; i < 8; i++) { float d = v[i] - mu; sq += d * d; }
    #pragma unroll
    for (int o = 16; o; o >>= 1) sq += __shfl_xor_sync(0xffffffffu, sq, o);
    float inv = 1.0f / sqrtf(sq / (float)DOUT + 1e-5f);

    const float* gp = ng + (long)e * DOUT;
    const float* bp = nb + (long)e * DOUT;
    float* op = outMain + (size_t)t * DOUT;
    #pragma unroll
    for (int i = 0; i < 8; i++) {
        int c = lane + i * 32;
        op[c] = (v[i] - mu) * inv * gp[c] + bp[c];
    }
}

// ---------------- launch ----------------------------------------------------------
extern "C" void kernel_launch(void* const* d_in, const int* in_sizes, int n_in,
                              void* d_out, int out_size)
{
    const float* x      = (const float*)d_in[0];
    const float* gumbel = (const float*)d_in[1];
    const float* rw1  = (const float*)d_in[2];
    const float* rb1  = (const float*)d_in[3];
    const float* rg1  = (const float*)d_in[4];
    const float* rbe1 = (const float*)d_in[5];
    const float* rw2  = (const float*)d_in[6];
    const float* rb2  = (const float*)d_in[7];
    const float* rg2  = (const float*)d_in[8];
    const float* rbe2 = (const float*)d_in[9];
    const float* rw3  = (const float*)d_in[10];
    const float* rb3  = (const float*)d_in[11];
    const float* ew1  = (const float*)d_in[12];
    const float* eb1  = (const float*)d_in[13];
    const float* eg1  = (const float*)d_in[14];
    const float* ebe1 = (const float*)d_in[15];
    const float* ew2  = (const float*)d_in[16];
    const float* eb2  = (const float*)d_in[17];
    const float* eg2  = (const float*)d_in[18];
    const float* ebe2 = (const float*)d_in[19];
    const float* ew3  = (const float*)d_in[20];
    const float* eb3  = (const float*)d_in[21];
    const float* eg3  = (const float*)d_in[22];
    const float* ebe3 = (const float*)d_in[23];
    const float* wqkv = (const float*)d_in[24];
    const float* bqkv = (const float*)d_in[25];
    const float* wo   = (const float*)d_in[26];
    const float* bo   = (const float*)d_in[27];
    const float* ng   = (const float*)d_in[28];
    const float* nb   = (const float*)d_in[29];

    float* outMain = (float*)d_out;
    float* outRW   = outMain + (size_t)BT * DOUT;
    float* outIdx  = outRW   + (size_t)BT * NE;

    float *bufA, *bufB, *Yb, *wc, *bc; int *off, *perm, *rowexp; void* cntp;
    cudaGetSymbolAddress((void**)&bufA,   g_bufA);
    cudaGetSymbolAddress((void**)&bufB,   g_bufB);
    cudaGetSymbolAddress((void**)&Yb,     g_Y);
    cudaGetSymbolAddress((void**)&wc,     g_wc);
    cudaGetSymbolAddress((void**)&bc,     g_bc);
    cudaGetSymbolAddress((void**)&off,    g_off);
    cudaGetSymbolAddress((void**)&perm,   g_perm);
    cudaGetSymbolAddress((void**)&rowexp, g_rowexp);
    cudaGetSymbolAddress(&cntp,           g_cnt);

    cudaMemsetAsync(cntp, 0, NE * sizeof(int));
    fuse_wo_wv<<<dim3(1, DOUT, NE), 256>>>(wqkv, bqkv, wo, bo, wc, bc);

    // ---- router (split-tf32: fp32-level accuracy, argmax-safe) ----
    gemm_tc<1><<<dim3(BT / BM, DH / BN, 1), 256>>>(x, nullptr, rw1, rb1, bufA, DH, DIN,
                                                   nullptr, 0, 0, BT);
    ln_rows<<<BT / 8, 256>>>(bufA, bufA, DH, rg1, rbe1, 0, 1, nullptr, BT);
    gemm_tc<1><<<dim3(BT / BM, (DH2 + BN - 1) / BN, 1), 256>>>(bufA, nullptr, rw2, rb2, bufB,
                                                               DH2, DH, nullptr, 0, 0, BT);
    ln_rows<<<BT / 8, 256>>>(bufB, bufB, DH2, rg2, rbe2, 0, 1, nullptr, BT);
    routing_kernel<<<BT / 8, 256>>>(bufB, rw3, rb3, gumbel, outRW, outIdx);
    scan_kernel<<<1, 32>>>();
    fill_perm<<<BT / 256, 256>>>();

    // ---- experts (compacted; plain tf32) ----
    gemm_tc<0><<<dim3(BT / BM, DH / BN, NE), 256>>>(x, perm, ew1, eb1, bufA, DH, DIN,
                                                    off, (long)DH * DIN, DH, BT);
    ln_rows<<<BT / 8, 256>>>(bufA, bufA, DH, eg1, ebe1, DH, 1, rowexp, BT);

    gemm_tc<0><<<dim3(BT / BM, DH / BN, NE), 256>>>(bufA, nullptr, ew2, eb2, bufB, DH, DH,
                                                    off, (long)DH * DH, DH, BT);
    ln_rows<<<BT / 8, 256>>>(bufB, bufB, DH, eg2, ebe2, DH, 1, rowexp, BT);

    gemm_tc<0><<<dim3(BT / BM, DOUT / BN, NE), 256>>>(bufB, nullptr, ew3, eb3, Yb, DOUT, DH,
                                                      off, (long)DOUT * DH, DOUT, BT);
    ln_rows<<<BT / 8, 256>>>(Yb, Yb, DOUT, eg3, ebe3, DOUT, 0, rowexp, BT);

    // attention over length-1 seq == V; V-proj and O-proj fused into wc/bc
    gemm_tc<0><<<dim3(BT / BM, DOUT / BN, NE), 256>>>(Yb, nullptr, wc, bc, bufA, DOUT, DOUT,
                                                      off, (long)DOUT * DOUT, DOUT, BT);

    final_kernel<<<BT / 8, 256>>>(Yb, bufA, ng, nb, outMain);
}